// round 9
// baseline (speedup 1.0000x reference)
#include <cuda_runtime.h>

// Problem constants
#define HH   512
#define WW   512
#define KK   51
#define PADK 25
#define PR   562          // padded rows
#define PSTR 576          // padded row stride (floats, 16B-aligned)
#define HWSZ (512*512)

// GEMM geometry: M=160 (3ch x 51 taps, padded), N=32 (x tile), K=88 (82 used)
#define MDIM 160
#define KDIM 88
#define KSTEPS 11         // K/8
#define ASTR 92           // A smem row stride (92 = -4 mod 32 -> conflict-free frags)
#define BSTR 40           // B smem row stride (40 = 8 mod 32 -> conflict-free frags)
#define CSTR 34           // C smem row stride (even -> STS.64 aligned)

// smem layout (float indices)
#define SA_F 0
#define SB_F (MDIM*ASTR)                 // 14720
#define SV_F (SB_F + KDIM*BSTR)          // 18240
#define SC_F (SV_F + KK*32)              // 19872
#define SMEM_FLOATS (SC_F + MDIM*CSTR)   // 25312
#define SMEM_BYTES (SMEM_FLOATS*4)       // 101248

// Pre-padded frames: [frame][batch][channel][row][col]  (15.5 MB scratch)
__device__ __align__(16) float g_pad[2][2][3][PR][PSTR];

// ---------------------------------------------------------------------------
// Pad kernel: replication-pad both frames into g_pad.
// ---------------------------------------------------------------------------
__global__ void pad_kernel(const float* __restrict__ f0,
                           const float* __restrict__ f2) {
    long idx = (long)blockIdx.x * blockDim.x + threadIdx.x;
    const long total = 2L * 2 * 3 * PR * PSTR;
    if (idx >= total) return;
    int col = (int)(idx % PSTR);
    long r  = idx / PSTR;
    int row = (int)(r % PR); r /= PR;
    int c   = (int)(r % 3);  r /= 3;
    int b   = (int)(r % 2);  r /= 2;
    int f   = (int)r;
    int sy = row - PADK; sy = sy < 0 ? 0 : (sy > HH - 1 ? HH - 1 : sy);
    int sx = col - PADK; sx = sx < 0 ? 0 : (sx > WW - 1 ? WW - 1 : sx);
    const float* src = f ? f2 : f0;
    g_pad[f][b][c][row][col] = src[((size_t)(b * 3 + c) * HH + sy) * WW + sx];
}

// ---------------------------------------------------------------------------
// PTX helpers
// ---------------------------------------------------------------------------
__device__ __forceinline__ void cp_async16(void* smem_dst, const void* gmem_src) {
    unsigned saddr = (unsigned)__cvta_generic_to_shared(smem_dst);
    asm volatile("cp.async.cg.shared.global [%0], [%1], 16;\n"
                 :: "r"(saddr), "l"(gmem_src));
}
__device__ __forceinline__ void cp_commit() {
    asm volatile("cp.async.commit_group;\n" ::: "memory");
}
__device__ __forceinline__ void cp_wait0() {
    asm volatile("cp.async.wait_group 0;\n" ::: "memory");
}
__device__ __forceinline__ unsigned f2tf(float f) {        // fp32 -> tf32 (RN)
    unsigned r;
    asm("cvt.rna.tf32.f32 %0, %1;" : "=r"(r) : "f"(f));
    return r;
}
__device__ __forceinline__ void mma_m16n8k8(float d[4],
                                            unsigned a0, unsigned a1,
                                            unsigned a2, unsigned a3,
                                            unsigned b0, unsigned b1) {
    asm volatile(
        "mma.sync.aligned.m16n8k8.row.col.f32.tf32.tf32.f32 "
        "{%0,%1,%2,%3}, {%4,%5,%6,%7}, {%8,%9}, {%0,%1,%2,%3};"
        : "+f"(d[0]), "+f"(d[1]), "+f"(d[2]), "+f"(d[3])
        : "r"(a0), "r"(a1), "r"(a2), "r"(a3), "r"(b0), "r"(b1));
}

// ---------------------------------------------------------------------------
// Main kernel: one CTA per (y, x-tile of 32, batch). 160 threads = 5 warps,
// each warp computes an m32n32 slab of C = A(P-window) x B(H-band) in tf32,
// then a 96-thread fp32 epilogue applies the vertical V reduction.
// ---------------------------------------------------------------------------
__global__ void __launch_bounds__(160, 2) sepconv_mma(
    const float* __restrict__ V1, const float* __restrict__ H1,
    const float* __restrict__ V2, const float* __restrict__ H2,
    float* __restrict__ out)
{
    extern __shared__ __align__(16) float smem[];
    float*    sA = smem + SA_F;      // [160][92] raw fp32
    unsigned* sB = (unsigned*)(smem + SB_F);   // [88][40] tf32 bits
    float*    sV = smem + SV_F;      // [51][32]
    float*    sC = smem + SC_F;      // [160][34]

    const int tid  = threadIdx.x;
    const int w    = tid >> 5;
    const int lane = tid & 31;
    const int g    = lane >> 2;      // groupID 0..7
    const int t4   = lane & 3;       // thread-in-group 0..3
    const int y  = blockIdx.x;
    const int xt = blockIdx.y * 32;
    const int b  = blockIdx.z;

    // Output accumulator (valid for tid < 96): c = tid/32, xl = tid%32
    const int ec = tid >> 5;         // reuse w; c for reduce when tid<96
    const int xl = tid & 31;
    float oacc = 0.0f;

    #pragma unroll 1
    for (int f = 0; f < 2; f++) {
        const float* Vf   = (f ? V2 : V1) + (size_t)b * KK * HWSZ;
        const float* Hf   = (f ? H2 : H1) + (size_t)b * KK * HWSZ;
        const float* padB = &g_pad[f][b][0][0][0];

        __syncthreads();   // previous iteration's readers of sA/sV/sB done

        // ---- Stage A: rows (c,i), 22 float4 per row ----
        #pragma unroll 1
        for (int u = tid; u < MDIM * 22; u += 160) {
            int r = u / 22, q = u - (u / 22) * 22;
            int rc = r > 152 ? 152 : r;                     // clamp pad rows
            int c = (rc >= 102) ? 2 : (rc >= 51 ? 1 : 0);
            int i = rc - c * 51;
            const float* src = padB + ((size_t)c * PR + (y + i)) * PSTR + xt + q * 4;
            cp_async16(sA + r * ASTR + q * 4, src);
        }
        // ---- Stage V: [51][32], 8 float4 per row ----
        #pragma unroll 1
        for (int u = tid; u < KK * 8; u += 160) {
            int i = u / 8, q = u - (u / 8) * 8;
            cp_async16(sV + i * 32 + q * 4,
                       Vf + (size_t)i * HWSZ + (size_t)y * WW + xt + q * 4);
        }
        cp_commit();

        // ---- Zero B ----
        #pragma unroll 1
        for (int u = tid; u < KDIM * BSTR; u += 160) sB[u] = 0u;
        __syncthreads();

        // ---- Fill B band: B[n+j][n] = tf32(H[j,y,xt+n]) ----
        {
            int n  = tid & 31;
            int jg = tid >> 5;                   // 0..4
            int j0 = jg * 11;
            int j1 = j0 + 11 > KK ? KK : j0 + 11;
            const float* hp = Hf + (size_t)y * WW + xt + n;
            #pragma unroll 1
            for (int j = j0; j < j1; j++)
                sB[(n + j) * BSTR + n] = f2tf(hp[(size_t)j * HWSZ]);
        }
        cp_wait0();
        __syncthreads();

        // ---- MMA phase: warp w owns rows [32w, 32w+32), all 32 cols ----
        float d[4][2][4];
        #pragma unroll
        for (int nb = 0; nb < 4; nb++)
            #pragma unroll
            for (int h = 0; h < 2; h++)
                #pragma unroll
                for (int e = 0; e < 4; e++) d[nb][h][e] = 0.0f;

        #pragma unroll 1
        for (int ks = 0; ks < KSTEPS; ks++) {
            const int col = ks * 8 + t4;
            unsigned a[2][4];
            #pragma unroll
            for (int h = 0; h < 2; h++) {
                const int r0 = 32 * w + 16 * h + g;
                a[h][0] = f2tf(sA[r0 * ASTR + col]);
                a[h][1] = f2tf(sA[(r0 + 8) * ASTR + col]);
                a[h][2] = f2tf(sA[r0 * ASTR + col + 4]);
                a[h][3] = f2tf(sA[(r0 + 8) * ASTR + col + 4]);
            }
            #pragma unroll
            for (int nb = 0; nb < 4; nb++) {
                unsigned b0 = sB[(ks * 8 + t4) * BSTR + 8 * nb + g];
                unsigned b1 = sB[(ks * 8 + t4 + 4) * BSTR + 8 * nb + g];
                mma_m16n8k8(d[nb][0], a[0][0], a[0][1], a[0][2], a[0][3], b0, b1);
                mma_m16n8k8(d[nb][1], a[1][0], a[1][1], a[1][2], a[1][3], b0, b1);
            }
        }

        // ---- Store C to smem ----
        #pragma unroll
        for (int nb = 0; nb < 4; nb++)
            #pragma unroll
            for (int h = 0; h < 2; h++) {
                const int r0  = 32 * w + 16 * h + g;
                const int cc  = 8 * nb + 2 * t4;
                *(float2*)&sC[r0 * CSTR + cc] =
                    make_float2(d[nb][h][0], d[nb][h][1]);
                *(float2*)&sC[(r0 + 8) * CSTR + cc] =
                    make_float2(d[nb][h][2], d[nb][h][3]);
            }
        __syncthreads();

        // ---- Reduce: out[c,x] += sum_i V[i,x] * C[51c+i, x] ----
        if (tid < 96) {
            const float* cp = sC + (size_t)(51 * ec) * CSTR + xl;
            const float* vp = sV + xl;
            float s = 0.0f;
            #pragma unroll
            for (int i = 0; i < KK; i++)
                s += vp[i * 32] * cp[i * CSTR];
            oacc += s;
        }
    }

    if (tid < 96)
        out[((size_t)(b * 3 + ec) * HH + y) * WW + xt + xl] = oacc;
}

// ---------------------------------------------------------------------------
// kernel_launch: inputs are frame0, frame2, V1, H1, V2, H2 (metadata order).
// ---------------------------------------------------------------------------
extern "C" void kernel_launch(void* const* d_in, const int* in_sizes, int n_in,
                              void* d_out, int out_size) {
    const float* frame0 = (const float*)d_in[0];
    const float* frame2 = (const float*)d_in[1];
    const float* V1     = (const float*)d_in[2];
    const float* H1     = (const float*)d_in[3];
    const float* V2     = (const float*)d_in[4];
    const float* H2     = (const float*)d_in[5];
    float* out = (float*)d_out;

    cudaFuncSetAttribute(sepconv_mma,
                         cudaFuncAttributeMaxDynamicSharedMemorySize, SMEM_BYTES);

    const long total = 2L * 2 * 3 * PR * PSTR;
    pad_kernel<<<(int)((total + 255) / 256), 256>>>(frame0, frame2);

    dim3 grid(HH, 16, 2);     // (y, x-tile, batch)
    sepconv_mma<<<grid, 160, SMEM_BYTES>>>(V1, H1, V2, H2, out);
}

// round 10
// speedup vs baseline: 1.2688x; 1.2688x over previous
#include <cuda_runtime.h>

// Problem constants
#define HH   512
#define WW   512
#define KK   51
#define PADK 25
#define PR   562          // padded rows
#define PSTR 576          // padded row stride (floats, 16B-aligned)
#define HWSZ (512*512)

// GEMM geometry: M=160 (3ch x 51 taps, padded), N=32 (x tile), K=88 (82 used)
#define MDIM 160
#define KDIM 88
#define KSTEPS 11         // K/8
#define ASTR 92           // A smem row stride (28g mod 32 pattern -> conflict-free)
#define BSTR 40           // B smem row stride
#define CSTR 34           // C smem row stride (aliased into sA region)

// smem layout (float indices). sC aliases sA (A dead after MMA).
#define SA_F 0
#define SB_F (MDIM*ASTR)                 // 14720
#define SMEM_FLOATS (SB_F + KDIM*BSTR)   // 18240
#define SMEM_BYTES (SMEM_FLOATS*4)       // 72960

#define NTHREADS 320      // 10 warps; warp w owns C rows [16w, 16w+16)

// Pre-padded frames: [frame][batch][channel][row][col]  (15.5 MB scratch)
__device__ __align__(16) float g_pad[2][2][3][PR][PSTR];

// ---------------------------------------------------------------------------
// Pad kernel: replication-pad both frames into g_pad.
// ---------------------------------------------------------------------------
__global__ void pad_kernel(const float* __restrict__ f0,
                           const float* __restrict__ f2) {
    long idx = (long)blockIdx.x * blockDim.x + threadIdx.x;
    const long total = 2L * 2 * 3 * PR * PSTR;
    if (idx >= total) return;
    int col = (int)(idx % PSTR);
    long r  = idx / PSTR;
    int row = (int)(r % PR); r /= PR;
    int c   = (int)(r % 3);  r /= 3;
    int b   = (int)(r % 2);  r /= 2;
    int f   = (int)r;
    int sy = row - PADK; sy = sy < 0 ? 0 : (sy > HH - 1 ? HH - 1 : sy);
    int sx = col - PADK; sx = sx < 0 ? 0 : (sx > WW - 1 ? WW - 1 : sx);
    const float* src = f ? f2 : f0;
    g_pad[f][b][c][row][col] = src[((size_t)(b * 3 + c) * HH + sy) * WW + sx];
}

// ---------------------------------------------------------------------------
// PTX helpers
// ---------------------------------------------------------------------------
__device__ __forceinline__ void cp_async16(void* smem_dst, const void* gmem_src) {
    unsigned saddr = (unsigned)__cvta_generic_to_shared(smem_dst);
    asm volatile("cp.async.cg.shared.global [%0], [%1], 16;\n"
                 :: "r"(saddr), "l"(gmem_src));
}
__device__ __forceinline__ void cp_commit() {
    asm volatile("cp.async.commit_group;\n" ::: "memory");
}
__device__ __forceinline__ void cp_wait0() {
    asm volatile("cp.async.wait_group 0;\n" ::: "memory");
}
__device__ __forceinline__ unsigned f2tf(float f) {        // fp32 -> tf32 (RN)
    unsigned r;
    asm("cvt.rna.tf32.f32 %0, %1;" : "=r"(r) : "f"(f));
    return r;
}
__device__ __forceinline__ void mma_m16n8k8(float d[4],
                                            unsigned a0, unsigned a1,
                                            unsigned a2, unsigned a3,
                                            unsigned b0, unsigned b1) {
    asm volatile(
        "mma.sync.aligned.m16n8k8.row.col.f32.tf32.tf32.f32 "
        "{%0,%1,%2,%3}, {%4,%5,%6,%7}, {%8,%9}, {%0,%1,%2,%3};"
        : "+f"(d[0]), "+f"(d[1]), "+f"(d[2]), "+f"(d[3])
        : "r"(a0), "r"(a1), "r"(a2), "r"(a3), "r"(b0), "r"(b1));
}

// ---------------------------------------------------------------------------
// Main kernel: one CTA per (y, x-tile of 32, batch). 320 threads = 10 warps,
// warp w computes the m16n32 slab C[16w..16w+16) of A(P-window) x B(H-band);
// a 96-thread fp32 epilogue applies the vertical V reduction (V from gmem).
// ---------------------------------------------------------------------------
__global__ void __launch_bounds__(NTHREADS, 2) sepconv_mma(
    const float* __restrict__ V1, const float* __restrict__ H1,
    const float* __restrict__ V2, const float* __restrict__ H2,
    float* __restrict__ out)
{
    extern __shared__ __align__(16) float smem[];
    float*    sA = smem + SA_F;                 // [160][92] raw fp32
    unsigned* sB = (unsigned*)(smem + SB_F);    // [88][40] tf32 bits
    float*    sC = smem + SA_F;                 // [160][34] — aliases sA

    const int tid  = threadIdx.x;
    const int w    = tid >> 5;
    const int lane = tid & 31;
    const int g    = lane >> 2;      // groupID 0..7
    const int t4   = lane & 3;       // thread-in-group 0..3
    const int y  = blockIdx.x;
    const int xt = blockIdx.y * 32;
    const int b  = blockIdx.z;

    const int ec = tid >> 5;         // channel for reduce when tid<96
    const int xl = tid & 31;
    float oacc = 0.0f;

    // Zero B once: the 51-wide band is overwritten per frame, complement stays 0.
    #pragma unroll 1
    for (int u = tid; u < KDIM * BSTR; u += NTHREADS) sB[u] = 0u;

    #pragma unroll 1
    for (int f = 0; f < 2; f++) {
        const float* Vf   = (f ? V2 : V1) + (size_t)b * KK * HWSZ;
        const float* Hf   = (f ? H2 : H1) + (size_t)b * KK * HWSZ;
        const float* padB = &g_pad[f][b][0][0][0];

        __syncthreads();   // previous reduce (sC) / B-readers done before restage

        // ---- Stage A (cp.async, 11 float4 per thread): rows (c,i), 22 f4/row ----
        #pragma unroll 1
        for (int u = tid; u < MDIM * 22; u += NTHREADS) {
            int r = u / 22, q = u - (u / 22) * 22;
            int rc = r > 152 ? 152 : r;                     // clamp pad rows
            int c = (rc >= 102) ? 2 : (rc >= 51 ? 1 : 0);
            int i = rc - c * 51;
            const float* src = padB + ((size_t)c * PR + (y + i)) * PSTR + xt + q * 4;
            cp_async16(sA + r * ASTR + q * 4, src);
        }
        cp_commit();

        // ---- Fill B band under the A flight: B[n+j][n] = tf32(H[j,y,xt+n]) ----
        {
            int n  = lane;
            int j0 = (w * KK) / 10;
            int j1 = ((w + 1) * KK) / 10;
            const float* hp = Hf + (size_t)y * WW + xt + n;
            #pragma unroll 1
            for (int j = j0; j < j1; j++)
                sB[(n + j) * BSTR + n] = f2tf(hp[(size_t)j * HWSZ]);
        }
        cp_wait0();
        __syncthreads();

        // ---- MMA: warp w owns rows [16w, 16w+16), all 32 cols ----
        float d[4][4];
        #pragma unroll
        for (int nb = 0; nb < 4; nb++)
            #pragma unroll
            for (int e = 0; e < 4; e++) d[nb][e] = 0.0f;

        const int r0 = 16 * w + g;
        #pragma unroll 1
        for (int ks = 0; ks < KSTEPS; ks++) {
            const int col = ks * 8 + t4;
            unsigned a0 = f2tf(sA[r0 * ASTR + col]);
            unsigned a1 = f2tf(sA[(r0 + 8) * ASTR + col]);
            unsigned a2 = f2tf(sA[r0 * ASTR + col + 4]);
            unsigned a3 = f2tf(sA[(r0 + 8) * ASTR + col + 4]);
            #pragma unroll
            for (int nb = 0; nb < 4; nb++) {
                unsigned b0 = sB[(ks * 8 + t4) * BSTR + 8 * nb + g];
                unsigned b1 = sB[(ks * 8 + t4 + 4) * BSTR + 8 * nb + g];
                mma_m16n8k8(d[nb], a0, a1, a2, a3, b0, b1);
            }
        }
        __syncthreads();   // all warps done READING sA before C overwrites it

        // ---- Store C into the (dead) sA region ----
        #pragma unroll
        for (int nb = 0; nb < 4; nb++) {
            const int cc = 8 * nb + 2 * t4;
            *(float2*)&sC[r0 * CSTR + cc]       = make_float2(d[nb][0], d[nb][1]);
            *(float2*)&sC[(r0 + 8) * CSTR + cc] = make_float2(d[nb][2], d[nb][3]);
        }
        __syncthreads();

        // ---- Reduce: out[c,x] += sum_i V[i,y,x] * C[51c+i, x]  (V from gmem) ----
        if (tid < 96) {
            const float* cp = sC + (size_t)(51 * ec) * CSTR + xl;
            const float* vp = Vf + (size_t)y * WW + xt + xl;
            float s = 0.0f;
            #pragma unroll
            for (int i = 0; i < KK; i++)
                s += vp[(size_t)i * HWSZ] * cp[i * CSTR];
            oacc += s;
        }
    }

    if (tid < 96)
        out[((size_t)(b * 3 + ec) * HH + y) * WW + xt + xl] = oacc;
}

// ---------------------------------------------------------------------------
// kernel_launch: inputs are frame0, frame2, V1, H1, V2, H2 (metadata order).
// ---------------------------------------------------------------------------
extern "C" void kernel_launch(void* const* d_in, const int* in_sizes, int n_in,
                              void* d_out, int out_size) {
    const float* frame0 = (const float*)d_in[0];
    const float* frame2 = (const float*)d_in[1];
    const float* V1     = (const float*)d_in[2];
    const float* H1     = (const float*)d_in[3];
    const float* V2     = (const float*)d_in[4];
    const float* H2     = (const float*)d_in[5];
    float* out = (float*)d_out;

    cudaFuncSetAttribute(sepconv_mma,
                         cudaFuncAttributeMaxDynamicSharedMemorySize, SMEM_BYTES);

    const long total = 2L * 2 * 3 * PR * PSTR;
    pad_kernel<<<(int)((total + 255) / 256), 256>>>(frame0, frame2);

    dim3 grid(HH, 16, 2);     // (y, x-tile, batch)
    sepconv_mma<<<grid, NTHREADS, SMEM_BYTES>>>(V1, H1, V2, H2, out);
}

// round 11
// speedup vs baseline: 1.6623x; 1.3102x over previous
#include <cuda_runtime.h>

// Problem constants
#define HH   512
#define WW   512
#define KK   51
#define PADK 25
#define PR   562          // padded rows (y+57 <= 561 for y0 max 504)
#define PSTR 576          // padded row stride (floats, 16B-aligned)
#define HWSZ (512*512)

// Tiling: TY output rows per CTA share one A stage
#define TY    8
#define MDIM  160         // GEMM M (3ch x 51 taps, padded to 160)
#define KDIM  88          // GEMM K (window cols; 82 used)
#define KSTEPS 11         // K/8
#define AROWS 174         // 3 ch x 58 padded rows staged
#define ASTR  92          // A smem row stride (conflict-free fragment loads)
#define BSTR  40          // B smem row stride
#define CSTR  34          // C smem row stride

// smem layout (float indices)
#define SA_F   0
#define SB_F   (AROWS*ASTR)              // 16008
#define SC_F   (SB_F + KDIM*BSTR)        // 19528
#define SO_F   (SC_F + MDIM*CSTR)        // 24968
#define SMEM_FLOATS (SO_F + 96*TY)       // 25736
#define SMEM_BYTES  (SMEM_FLOATS*4)      // 102944 (2 CTAs/SM = 201KB)

#define NTHREADS 320      // 10 warps; warp w owns C rows [16w, 16w+16)

// Pre-padded frames: [frame][batch][channel][row][col]  (15.5 MB scratch)
__device__ __align__(16) float g_pad[2][2][3][PR][PSTR];

// ---------------------------------------------------------------------------
// Pad kernel: replication-pad both frames into g_pad.
// ---------------------------------------------------------------------------
__global__ void pad_kernel(const float* __restrict__ f0,
                           const float* __restrict__ f2) {
    long idx = (long)blockIdx.x * blockDim.x + threadIdx.x;
    const long total = 2L * 2 * 3 * PR * PSTR;
    if (idx >= total) return;
    int col = (int)(idx % PSTR);
    long r  = idx / PSTR;
    int row = (int)(r % PR); r /= PR;
    int c   = (int)(r % 3);  r /= 3;
    int b   = (int)(r % 2);  r /= 2;
    int f   = (int)r;
    int sy = row - PADK; sy = sy < 0 ? 0 : (sy > HH - 1 ? HH - 1 : sy);
    int sx = col - PADK; sx = sx < 0 ? 0 : (sx > WW - 1 ? WW - 1 : sx);
    const float* src = f ? f2 : f0;
    g_pad[f][b][c][row][col] = src[((size_t)(b * 3 + c) * HH + sy) * WW + sx];
}

// ---------------------------------------------------------------------------
// PTX helpers
// ---------------------------------------------------------------------------
__device__ __forceinline__ void cp_async16(void* smem_dst, const void* gmem_src) {
    unsigned saddr = (unsigned)__cvta_generic_to_shared(smem_dst);
    asm volatile("cp.async.cg.shared.global [%0], [%1], 16;\n"
                 :: "r"(saddr), "l"(gmem_src));
}
__device__ __forceinline__ void cp_commit() {
    asm volatile("cp.async.commit_group;\n" ::: "memory");
}
__device__ __forceinline__ void cp_wait0() {
    asm volatile("cp.async.wait_group 0;\n" ::: "memory");
}
__device__ __forceinline__ unsigned f2tf(float f) {        // fp32 -> tf32 (RN)
    unsigned r;
    asm("cvt.rna.tf32.f32 %0, %1;" : "=r"(r) : "f"(f));
    return r;
}
__device__ __forceinline__ void mma_m16n8k8(float d[4],
                                            unsigned a0, unsigned a1,
                                            unsigned a2, unsigned a3,
                                            unsigned b0, unsigned b1) {
    asm volatile(
        "mma.sync.aligned.m16n8k8.row.col.f32.tf32.tf32.f32 "
        "{%0,%1,%2,%3}, {%4,%5,%6,%7}, {%8,%9}, {%0,%1,%2,%3};"
        : "+f"(d[0]), "+f"(d[1]), "+f"(d[2]), "+f"(d[3])
        : "r"(a0), "r"(a1), "r"(a2), "r"(a3), "r"(b0), "r"(b1));
}

// ---------------------------------------------------------------------------
// Main kernel: one CTA per (8-row y block, x-tile of 32, batch).
// A (3ch x 58 padded rows x 88 cols) staged ONCE per frame and reused by the
// 8 per-row banded GEMMs (row offset dy). B band rebuilt per dy; epilogue
// accumulates into smem across frames.
// ---------------------------------------------------------------------------
__global__ void __launch_bounds__(NTHREADS, 2) sepconv_mma(
    const float* __restrict__ V1, const float* __restrict__ H1,
    const float* __restrict__ V2, const float* __restrict__ H2,
    float* __restrict__ out)
{
    extern __shared__ __align__(16) float smem[];
    float*    sA = smem + SA_F;                 // [174][92] raw fp32
    unsigned* sB = (unsigned*)(smem + SB_F);    // [88][40] tf32 bits
    float*    sC = smem + SC_F;                 // [160][34]
    float*    so = smem + SO_F;                 // [TY][96] output accumulators

    const int tid  = threadIdx.x;
    const int w    = tid >> 5;
    const int lane = tid & 31;
    const int g    = lane >> 2;      // groupID 0..7
    const int t4   = lane & 3;       // thread-in-group 0..3
    const int y0 = blockIdx.x * TY;
    const int xt = blockIdx.y * 32;
    const int b  = blockIdx.z;

    // Fragment row mapping: GEMM row m -> staged A row (c*58 + i) + dy
    const int r0 = 16 * w + g;                       // 0..151
    const int rB = (r0 + 8 > 152) ? 152 : r0 + 8;    // clamp pad rows
    const int cA = (r0 >= 102) ? 2 : (r0 >= 51 ? 1 : 0);
    const int cB = (rB >= 102) ? 2 : (rB >= 51 ? 1 : 0);
    const int baseA = cA * 58 + (r0 - 51 * cA);
    const int baseB = cB * 58 + (rB - 51 * cB);

    const int ec = tid >> 5;         // channel for reduce when tid<96
    const int xl = tid & 31;

    // B-band j range per warp
    const int j0 = (w * KK) / 10;
    const int j1 = ((w + 1) * KK) / 10;

    // Zero B (band overwritten each dy; complement stays 0) and accumulators
    #pragma unroll 1
    for (int u = tid; u < KDIM * BSTR; u += NTHREADS) sB[u] = 0u;
    #pragma unroll 1
    for (int u = tid; u < 96 * TY; u += NTHREADS) so[u] = 0.0f;

    #pragma unroll 1
    for (int f = 0; f < 2; f++) {
        const float* Vf   = (f ? V2 : V1) + (size_t)b * KK * HWSZ;
        const float* Hf   = (f ? H2 : H1) + (size_t)b * KK * HWSZ;
        const float* padB = &g_pad[f][b][0][0][0];

        // ---- Stage A once per frame: 174 rows x 22 float4 ----
        #pragma unroll 1
        for (int u = tid; u < AROWS * 22; u += NTHREADS) {
            int r = u / 22, q = u - r * 22;
            int c = r / 58, rr = r - c * 58;
            cp_async16(sA + r * ASTR + q * 4,
                       padB + ((size_t)c * PR + (y0 + rr)) * PSTR + xt + q * 4);
        }
        cp_commit();

        #pragma unroll 1
        for (int dy = 0; dy < TY; dy++) {
            // ---- Fill B band for this output row: B[n+j][n]=tf32(H[j,y0+dy,xt+n])
            {
                const float* hp = Hf + (size_t)(y0 + dy) * WW + xt + lane;
                #pragma unroll 1
                for (int j = j0; j < j1; j++)
                    sB[(lane + j) * BSTR + lane] = f2tf(hp[(size_t)j * HWSZ]);
            }
            if (dy == 0) cp_wait0();
            __syncthreads();            // B + A visible; prior sC readers done

            // ---- MMA: warp w computes C rows [16w,16w+16), 32 cols ----
            float d[4][4];
            #pragma unroll
            for (int nb = 0; nb < 4; nb++)
                #pragma unroll
                for (int e = 0; e < 4; e++) d[nb][e] = 0.0f;

            const int sa0 = (baseA + dy) * ASTR;
            const int sa1 = (baseB + dy) * ASTR;
            #pragma unroll 1
            for (int ks = 0; ks < KSTEPS; ks++) {
                const int col = ks * 8 + t4;
                unsigned a0 = f2tf(sA[sa0 + col]);
                unsigned a1 = f2tf(sA[sa1 + col]);
                unsigned a2 = f2tf(sA[sa0 + col + 4]);
                unsigned a3 = f2tf(sA[sa1 + col + 4]);
                #pragma unroll
                for (int nb = 0; nb < 4; nb++) {
                    unsigned b0 = sB[(ks * 8 + t4) * BSTR + 8 * nb + g];
                    unsigned b1 = sB[(ks * 8 + t4 + 4) * BSTR + 8 * nb + g];
                    mma_m16n8k8(d[nb], a0, a1, a2, a3, b0, b1);
                }
            }

            // ---- Store C ----
            #pragma unroll
            for (int nb = 0; nb < 4; nb++) {
                const int cc = 8 * nb + 2 * t4;
                *(float2*)&sC[r0 * CSTR + cc]       = make_float2(d[nb][0], d[nb][1]);
                *(float2*)&sC[(r0 + 8) * CSTR + cc] = make_float2(d[nb][2], d[nb][3]);
            }
            __syncthreads();            // C visible; B readers done

            // ---- Reduce this output row: so[dy][c,x] += sum_i V[i]*C[51c+i,x]
            if (tid < 96) {
                const float* cp_ = sC + (size_t)(51 * ec) * CSTR + xl;
                const float* vp  = Vf + (size_t)(y0 + dy) * WW + xt + xl;
                float s = 0.0f;
                #pragma unroll
                for (int i = 0; i < KK; i++)
                    s += vp[(size_t)i * HWSZ] * cp_[i * CSTR];
                so[dy * 96 + tid] += s;
            }
            // next dy's fillB touches only sB; sC overwrite guarded by sync#1
        }
    }
    __syncthreads();

    if (tid < 96) {
        #pragma unroll
        for (int dy = 0; dy < TY; dy++)
            out[((size_t)(b * 3 + ec) * HH + (y0 + dy)) * WW + xt + xl] =
                so[dy * 96 + tid];
    }
}

// ---------------------------------------------------------------------------
// kernel_launch: inputs are frame0, frame2, V1, H1, V2, H2 (metadata order).
// ---------------------------------------------------------------------------
extern "C" void kernel_launch(void* const* d_in, const int* in_sizes, int n_in,
                              void* d_out, int out_size) {
    const float* frame0 = (const float*)d_in[0];
    const float* frame2 = (const float*)d_in[1];
    const float* V1     = (const float*)d_in[2];
    const float* H1     = (const float*)d_in[3];
    const float* V2     = (const float*)d_in[4];
    const float* H2     = (const float*)d_in[5];
    float* out = (float*)d_out;

    cudaFuncSetAttribute(sepconv_mma,
                         cudaFuncAttributeMaxDynamicSharedMemorySize, SMEM_BYTES);

    const long total = 2L * 2 * 3 * PR * PSTR;
    pad_kernel<<<(int)((total + 255) / 256), 256>>>(frame0, frame2);

    dim3 grid(HH / TY, 16, 2);     // (y block, x-tile, batch)
    sepconv_mma<<<grid, NTHREADS, SMEM_BYTES>>>(V1, H1, V2, H2, out);
}

// round 12
// speedup vs baseline: 2.6526x; 1.5958x over previous
#include <cuda_runtime.h>

// Problem constants
#define HH   512
#define WW   512
#define KK   51
#define PADK 25
#define PR   562          // padded rows
#define PSTR 576          // padded row stride (floats, 16B-aligned)
#define HWSZ (512*512)

// Tiling: TY output rows per CTA share one A stage
#define TY    8
#define KSTEPS 11         // GEMM K = 88 (82 used)
#define AROWS 174         // 3 ch x 58 padded rows staged
#define ASTR  92          // A smem row stride (conflict-free fragment loads)
#define BSTR  40          // B smem row stride (8 mod 32 -> conflict-free)
#define CSTR  34          // C smem row stride

// smem layout (float indices)
#define SA_F   0
#define SB_F   (AROWS*ASTR)              // 16008
#define SC_F   (SB_F + 88*BSTR)          // 19528
#define SV_F   (SC_F + 160*CSTR)         // 24968
#define SH_F   (SV_F + KK*32)            // 26600
#define SMEM_FLOATS (SH_F + KK*32)       // 28232
#define SMEM_BYTES  (SMEM_FLOATS*4)      // 112928 -> 2 CTAs/SM

#define NTHREADS 320      // 10 warps; warp w owns C rows [16w, 16w+16)

// Pre-padded frames: [frame][batch][channel][row][col]  (15.5 MB scratch)
__device__ __align__(16) float g_pad[2][2][3][PR][PSTR];

// ---------------------------------------------------------------------------
// Pad kernel: replication-pad both frames into g_pad.
// ---------------------------------------------------------------------------
__global__ void pad_kernel(const float* __restrict__ f0,
                           const float* __restrict__ f2) {
    long idx = (long)blockIdx.x * blockDim.x + threadIdx.x;
    const long total = 2L * 2 * 3 * PR * PSTR;
    if (idx >= total) return;
    int col = (int)(idx % PSTR);
    long r  = idx / PSTR;
    int row = (int)(r % PR); r /= PR;
    int c   = (int)(r % 3);  r /= 3;
    int b   = (int)(r % 2);  r /= 2;
    int f   = (int)r;
    int sy = row - PADK; sy = sy < 0 ? 0 : (sy > HH - 1 ? HH - 1 : sy);
    int sx = col - PADK; sx = sx < 0 ? 0 : (sx > WW - 1 ? WW - 1 : sx);
    const float* src = f ? f2 : f0;
    g_pad[f][b][c][row][col] = src[((size_t)(b * 3 + c) * HH + sy) * WW + sx];
}

// ---------------------------------------------------------------------------
// PTX helpers
// ---------------------------------------------------------------------------
__device__ __forceinline__ void cp_async16(void* smem_dst, const void* gmem_src) {
    unsigned saddr = (unsigned)__cvta_generic_to_shared(smem_dst);
    asm volatile("cp.async.cg.shared.global [%0], [%1], 16;\n"
                 :: "r"(saddr), "l"(gmem_src));
}
__device__ __forceinline__ void cp_commit() {
    asm volatile("cp.async.commit_group;\n" ::: "memory");
}
__device__ __forceinline__ void cp_wait0() {
    asm volatile("cp.async.wait_group 0;\n" ::: "memory");
}
__device__ __forceinline__ unsigned f2tf(float f) {        // fp32 -> tf32 (RN)
    unsigned r;
    asm("cvt.rna.tf32.f32 %0, %1;" : "=r"(r) : "f"(f));
    return r;
}
__device__ __forceinline__ void mma_m16n8k8(float d[4],
                                            unsigned a0, unsigned a1,
                                            unsigned a2, unsigned a3,
                                            unsigned b0, unsigned b1) {
    asm volatile(
        "mma.sync.aligned.m16n8k8.row.col.f32.tf32.tf32.f32 "
        "{%0,%1,%2,%3}, {%4,%5,%6,%7}, {%8,%9}, {%0,%1,%2,%3};"
        : "+f"(d[0]), "+f"(d[1]), "+f"(d[2]), "+f"(d[3])
        : "r"(a0), "r"(a1), "r"(a2), "r"(a3), "r"(b0), "r"(b1));
}

// ---------------------------------------------------------------------------
// Main kernel: one CTA per (8-row y block, x-tile of 32, batch).
// A staged once per frame (then tf32-converted in place); per dy: H band from
// smem (prefetched), banded MMA, V-weighted reduce with V from smem
// (prefetched under the MMA shadow). Cross-frame accumulate via gmem RMW.
// ---------------------------------------------------------------------------
__global__ void __launch_bounds__(NTHREADS, 2) sepconv_mma(
    const float* __restrict__ V1, const float* __restrict__ H1,
    const float* __restrict__ V2, const float* __restrict__ H2,
    float* __restrict__ out)
{
    extern __shared__ __align__(16) float smem[];
    float*    sA  = smem + SA_F;                // [174][92] fp32, then tf32 bits
    unsigned* sAu = (unsigned*)(smem + SA_F);
    unsigned* sB  = (unsigned*)(smem + SB_F);   // [88][40] tf32 bits
    float*    sC  = smem + SC_F;                // [160][34]
    float*    sV  = smem + SV_F;                // [51][32] V taps (this dy)
    float*    sH  = smem + SH_F;                // [51][32] H taps (next fillB)

    const int tid  = threadIdx.x;
    const int w    = tid >> 5;
    const int lane = tid & 31;
    const int g    = lane >> 2;      // groupID 0..7
    const int t4   = lane & 3;       // thread-in-group 0..3
    const int y0 = blockIdx.x * TY;
    const int xt = blockIdx.y * 32;
    const int b  = blockIdx.z;

    // Fragment row mapping: GEMM row m -> staged A row (c*58 + i) + dy
    const int r0 = 16 * w + g;                       // 0..151
    const int rB = (r0 + 8 > 152) ? 152 : r0 + 8;    // clamp pad rows
    const int cA = (r0 >= 102) ? 2 : (r0 >= 51 ? 1 : 0);
    const int cB = (rB >= 102) ? 2 : (rB >= 51 ? 1 : 0);
    const int baseA = cA * 58 + (r0 - 51 * cA);
    const int baseB = cB * 58 + (rB - 51 * cB);

    const int ec = tid >> 5;         // channel for reduce when tid<96
    const int xl = tid & 31;

    // B-band j range per warp
    const int j0 = (w * KK) / 10;
    const int j1 = ((w + 1) * KK) / 10;

    // Zero B (band overwritten each dy; complement stays 0)
    #pragma unroll 1
    for (int u = tid; u < 88 * BSTR; u += NTHREADS) sB[u] = 0u;

    // Prologue: prefetch H(frame0, dy0) into sH
    {
        const float* h0 = H1 + (size_t)b * KK * HWSZ + (size_t)y0 * WW + xt;
        #pragma unroll 1
        for (int u = tid; u < KK * 8; u += NTHREADS) {
            int i = u >> 3, q = u & 7;
            cp_async16(sH + i * 32 + q * 4, h0 + (size_t)i * HWSZ + q * 4);
        }
        cp_commit();
    }

    #pragma unroll 1
    for (int f = 0; f < 2; f++) {
        const float* Vf   = (f ? V2 : V1) + (size_t)b * KK * HWSZ;
        const float* Hf   = (f ? H2 : H1) + (size_t)b * KK * HWSZ;
        const float* HfN  = H2 + (size_t)b * KK * HWSZ;   // next-frame H (f==0)
        const float* padB = &g_pad[f][b][0][0][0];

        // ---- Stage A once per frame: 174 rows x 22 float4 ----
        #pragma unroll 1
        for (int u = tid; u < AROWS * 22; u += NTHREADS) {
            int r = u / 22, q = u - r * 22;
            int c = r / 58, rr = r - c * 58;
            cp_async16(sA + r * ASTR + q * 4,
                       padB + ((size_t)c * PR + (y0 + rr)) * PSTR + xt + q * 4);
        }
        cp_commit();

        #pragma unroll 1
        for (int dy = 0; dy < TY; dy++) {
            if (dy == 0) {
                cp_wait0();
                __syncthreads();     // A (+H at f==0) visible to all threads
                // One-time in-place tf32 convert of sA (saves cvt in MMA chain)
                #pragma unroll 1
                for (int u = tid; u < AROWS * 22; u += NTHREADS) {
                    int r = u / 22, q = u - r * 22;
                    float4* p = (float4*)(sA + r * ASTR + q * 4);
                    float4 v = *p;
                    uint4 t;
                    t.x = f2tf(v.x); t.y = f2tf(v.y);
                    t.z = f2tf(v.z); t.w = f2tf(v.w);
                    *(uint4*)p = t;
                }
            }

            // ---- Fill B band from smem H: B[n+j][n] = tf32(sH[j][n]) ----
            #pragma unroll 1
            for (int j = j0; j < j1; j++)
                sB[(lane + j) * BSTR + lane] = f2tf(sH[j * 32 + lane]);
            __syncthreads();         // barrier1: B + converted A ready

            // ---- Prefetch V(f,dy) and H(next) under the MMA shadow ----
            {
                const float* vsrc = Vf + (size_t)(y0 + dy) * WW + xt;
                #pragma unroll 1
                for (int u = tid; u < KK * 8; u += NTHREADS) {
                    int i = u >> 3, q = u & 7;
                    cp_async16(sV + i * 32 + q * 4, vsrc + (size_t)i * HWSZ + q * 4);
                }
                if (!(f == 1 && dy == TY - 1)) {
                    const float* hsrc = (dy < TY - 1)
                        ? Hf  + (size_t)(y0 + dy + 1) * WW + xt
                        : HfN + (size_t)y0 * WW + xt;
                    #pragma unroll 1
                    for (int u = tid; u < KK * 8; u += NTHREADS) {
                        int i = u >> 3, q = u & 7;
                        cp_async16(sH + i * 32 + q * 4, hsrc + (size_t)i * HWSZ + q * 4);
                    }
                }
                cp_commit();
            }

            // ---- MMA: warp w computes C rows [16w,16w+16), 32 cols ----
            float d[4][4];
            #pragma unroll
            for (int nb = 0; nb < 4; nb++)
                #pragma unroll
                for (int e = 0; e < 4; e++) d[nb][e] = 0.0f;

            const int sa0 = (baseA + dy) * ASTR;
            const int sa1 = (baseB + dy) * ASTR;
            #pragma unroll 1
            for (int ks = 0; ks < KSTEPS; ks++) {
                const int col = ks * 8 + t4;
                unsigned a0 = sAu[sa0 + col];
                unsigned a1 = sAu[sa1 + col];
                unsigned a2 = sAu[sa0 + col + 4];
                unsigned a3 = sAu[sa1 + col + 4];
                #pragma unroll
                for (int nb = 0; nb < 4; nb++) {
                    unsigned b0 = sB[(ks * 8 + t4) * BSTR + 8 * nb + g];
                    unsigned b1 = sB[(ks * 8 + t4 + 4) * BSTR + 8 * nb + g];
                    mma_m16n8k8(d[nb], a0, a1, a2, a3, b0, b1);
                }
            }

            // ---- Store C ----
            #pragma unroll
            for (int nb = 0; nb < 4; nb++) {
                const int cc = 8 * nb + 2 * t4;
                *(float2*)&sC[r0 * CSTR + cc]       = make_float2(d[nb][0], d[nb][1]);
                *(float2*)&sC[(r0 + 8) * CSTR + cc] = make_float2(d[nb][2], d[nb][3]);
            }

            cp_wait0();              // V (+ next H) landed
            __syncthreads();         // barrier2: C + V + H visible

            // ---- Reduce: out(c,x) (+)= sum_i sV[i,x] * C[51c+i, x] ----
            if (tid < 96) {
                const float* cp_ = sC + (size_t)(51 * ec) * CSTR + xl;
                const float* vp  = sV + xl;
                float s0 = 0.0f, s1 = 0.0f;
                #pragma unroll
                for (int i = 0; i < 50; i += 2) {
                    s0 += vp[i * 32]       * cp_[i * CSTR];
                    s1 += vp[(i + 1) * 32] * cp_[(i + 1) * CSTR];
                }
                s0 += vp[50 * 32] * cp_[50 * CSTR];
                float s = s0 + s1;
                float* op = out + ((size_t)(b * 3 + ec) * HH + (y0 + dy)) * WW + xt + xl;
                if (f == 0) *op = s;
                else        *op = *op + s;      // same thread wrote it in f==0
            }
        }
    }
}

// ---------------------------------------------------------------------------
// kernel_launch: inputs are frame0, frame2, V1, H1, V2, H2 (metadata order).
// ---------------------------------------------------------------------------
extern "C" void kernel_launch(void* const* d_in, const int* in_sizes, int n_in,
                              void* d_out, int out_size) {
    const float* frame0 = (const float*)d_in[0];
    const float* frame2 = (const float*)d_in[1];
    const float* V1     = (const float*)d_in[2];
    const float* H1     = (const float*)d_in[3];
    const float* V2     = (const float*)d_in[4];
    const float* H2     = (const float*)d_in[5];
    float* out = (float*)d_out;

    cudaFuncSetAttribute(sepconv_mma,
                         cudaFuncAttributeMaxDynamicSharedMemorySize, SMEM_BYTES);

    const long total = 2L * 2 * 3 * PR * PSTR;
    pad_kernel<<<(int)((total + 255) / 256), 256>>>(frame0, frame2);

    dim3 grid(HH / TY, 16, 2);     // (y block, x-tile, batch)
    sepconv_mma<<<grid, NTHREADS, SMEM_BYTES>>>(V1, H1, V2, H2, out);
}

// round 13
// speedup vs baseline: 2.8052x; 1.0575x over previous
#include <cuda_runtime.h>

// Problem constants
#define HH   512
#define WW   512
#define KK   51
#define PADK 25
#define PR   562          // padded rows
#define PSTR 576          // padded row stride (floats, 16B-aligned)
#define HWSZ (512*512)

// Tiling: TY output rows per CTA share one A stage
#define TY    8
#define AROWS 174         // 3 ch x 58 padded rows staged
#define ASTR  92          // A smem row stride (conflict-free fragment loads)
#define BSTR  40          // B smem row stride (8 mod 32 -> conflict-free)
#define CSTR  34          // C smem row stride

// smem layout (float indices)
#define SA_F   0
#define SB_F   (AROWS*ASTR)              // 16008
#define SC_F   (SB_F + 88*BSTR)          // 19528
#define SV_F   (SC_F + 160*CSTR)         // 24968
#define SH_F   (SV_F + KK*32)            // 26600
#define SMEM_FLOATS (SH_F + KK*32)       // 28232
#define SMEM_BYTES  (SMEM_FLOATS*4)      // 112928 -> 2 CTAs/SM

#define NTHREADS 320      // 10 warps; warp w owns C rows [16w, 16w+16)

// Pre-padded frames: [frame][batch][channel][row][col]  (15.5 MB scratch)
__device__ __align__(16) float g_pad[2][2][3][PR][PSTR];

// ---------------------------------------------------------------------------
// Pad kernel: replication-pad both frames into g_pad.
// ---------------------------------------------------------------------------
__global__ void pad_kernel(const float* __restrict__ f0,
                           const float* __restrict__ f2) {
    long idx = (long)blockIdx.x * blockDim.x + threadIdx.x;
    const long total = 2L * 2 * 3 * PR * PSTR;
    if (idx >= total) return;
    int col = (int)(idx % PSTR);
    long r  = idx / PSTR;
    int row = (int)(r % PR); r /= PR;
    int c   = (int)(r % 3);  r /= 3;
    int b   = (int)(r % 2);  r /= 2;
    int f   = (int)r;
    int sy = row - PADK; sy = sy < 0 ? 0 : (sy > HH - 1 ? HH - 1 : sy);
    int sx = col - PADK; sx = sx < 0 ? 0 : (sx > WW - 1 ? WW - 1 : sx);
    const float* src = f ? f2 : f0;
    g_pad[f][b][c][row][col] = src[((size_t)(b * 3 + c) * HH + sy) * WW + sx];
}

// ---------------------------------------------------------------------------
// PTX helpers
// ---------------------------------------------------------------------------
__device__ __forceinline__ void cp_async16(void* smem_dst, const void* gmem_src) {
    unsigned saddr = (unsigned)__cvta_generic_to_shared(smem_dst);
    asm volatile("cp.async.cg.shared.global [%0], [%1], 16;\n"
                 :: "r"(saddr), "l"(gmem_src));
}
__device__ __forceinline__ void cp_commit() {
    asm volatile("cp.async.commit_group;\n" ::: "memory");
}
__device__ __forceinline__ void cp_wait0() {
    asm volatile("cp.async.wait_group 0;\n" ::: "memory");
}
__device__ __forceinline__ unsigned f2tf(float f) {        // fp32 -> tf32 (RN)
    unsigned r;
    asm("cvt.rna.tf32.f32 %0, %1;" : "=r"(r) : "f"(f));
    return r;
}
__device__ __forceinline__ void mma_m16n8k8(float d[4],
                                            unsigned a0, unsigned a1,
                                            unsigned a2, unsigned a3,
                                            unsigned b0, unsigned b1) {
    asm volatile(
        "mma.sync.aligned.m16n8k8.row.col.f32.tf32.tf32.f32 "
        "{%0,%1,%2,%3}, {%4,%5,%6,%7}, {%8,%9}, {%0,%1,%2,%3};"
        : "+f"(d[0]), "+f"(d[1]), "+f"(d[2]), "+f"(d[3])
        : "r"(a0), "r"(a1), "r"(a2), "r"(a3), "r"(b0), "r"(b1));
}

// ---------------------------------------------------------------------------
// Main kernel: one CTA per (8-row y block, x-tile of 32, batch).
// Banded tf32 GEMM per output row; band-aware split-K skips the k-steps that
// only touch the zero band-complement (n<16 -> ks 0..8, n>=16 -> ks 2..10).
// ---------------------------------------------------------------------------
__global__ void __launch_bounds__(NTHREADS, 2) sepconv_mma(
    const float* __restrict__ V1, const float* __restrict__ H1,
    const float* __restrict__ V2, const float* __restrict__ H2,
    float* __restrict__ out)
{
    extern __shared__ __align__(16) float smem[];
    float*    sA  = smem + SA_F;                // [174][92] fp32, then tf32 bits
    unsigned* sAu = (unsigned*)(smem + SA_F);
    unsigned* sB  = (unsigned*)(smem + SB_F);   // [88][40] tf32 bits
    float*    sC  = smem + SC_F;                // [160][34]
    float*    sV  = smem + SV_F;                // [51][32] V taps (this dy)
    float*    sH  = smem + SH_F;                // [51][32] H taps (next fillB)

    const int tid  = threadIdx.x;
    const int w    = tid >> 5;
    const int lane = tid & 31;
    const int g    = lane >> 2;      // groupID 0..7
    const int t4   = lane & 3;       // thread-in-group 0..3
    const int y0 = blockIdx.x * TY;
    const int xt = blockIdx.y * 32;
    const int b  = blockIdx.z;

    // Fragment row mapping: GEMM row m -> staged A row (c*58 + i) + dy
    const int r0 = 16 * w + g;                       // 0..151
    const int rB = (r0 + 8 > 152) ? 152 : r0 + 8;    // clamp pad rows
    const int cA = (r0 >= 102) ? 2 : (r0 >= 51 ? 1 : 0);
    const int cB = (rB >= 102) ? 2 : (rB >= 51 ? 1 : 0);
    const int baseA = cA * 58 + (r0 - 51 * cA);
    const int baseB = cB * 58 + (rB - 51 * cB);

    const int ec = tid >> 5;         // channel for reduce when tid<96
    const int xl = tid & 31;

    // B-band j range per warp
    const int j0 = (w * KK) / 10;
    const int j1 = ((w + 1) * KK) / 10;

    // Zero B (band overwritten each dy; complement stays 0)
    #pragma unroll 1
    for (int u = tid; u < 88 * BSTR; u += NTHREADS) sB[u] = 0u;

    // Prologue: prefetch H(frame0, dy0) into sH
    {
        const float* h0 = H1 + (size_t)b * KK * HWSZ + (size_t)y0 * WW + xt;
        #pragma unroll 1
        for (int u = tid; u < KK * 8; u += NTHREADS) {
            int i = u >> 3, q = u & 7;
            cp_async16(sH + i * 32 + q * 4, h0 + (size_t)i * HWSZ + q * 4);
        }
        cp_commit();
    }

    #pragma unroll 1
    for (int f = 0; f < 2; f++) {
        const float* Vf   = (f ? V2 : V1) + (size_t)b * KK * HWSZ;
        const float* Hf   = (f ? H2 : H1) + (size_t)b * KK * HWSZ;
        const float* HfN  = H2 + (size_t)b * KK * HWSZ;   // next-frame H (f==0)
        const float* padB = &g_pad[f][b][0][0][0];

        // ---- Stage A once per frame: 174 rows x 22 float4 ----
        #pragma unroll 1
        for (int u = tid; u < AROWS * 22; u += NTHREADS) {
            int r = u / 22, q = u - r * 22;
            int c = r / 58, rr = r - c * 58;
            cp_async16(sA + r * ASTR + q * 4,
                       padB + ((size_t)c * PR + (y0 + rr)) * PSTR + xt + q * 4);
        }
        cp_commit();

        #pragma unroll 1
        for (int dy = 0; dy < TY; dy++) {
            if (dy == 0) {
                cp_wait0();
                __syncthreads();     // A (+H at f==0) visible to all threads
                // One-time in-place tf32 convert of sA
                #pragma unroll 1
                for (int u = tid; u < AROWS * 22; u += NTHREADS) {
                    int r = u / 22, q = u - r * 22;
                    float4* p = (float4*)(sA + r * ASTR + q * 4);
                    float4 v = *p;
                    uint4 t;
                    t.x = f2tf(v.x); t.y = f2tf(v.y);
                    t.z = f2tf(v.z); t.w = f2tf(v.w);
                    *(uint4*)p = t;
                }
            }

            // ---- Fill B band from smem H: B[n+j][n] = tf32(sH[j][n]) ----
            #pragma unroll 1
            for (int j = j0; j < j1; j++)
                sB[(lane + j) * BSTR + lane] = f2tf(sH[j * 32 + lane]);
            __syncthreads();         // barrier1: B + converted A ready

            // ---- Prefetch V(f,dy) and H(next) under the MMA shadow ----
            {
                const float* vsrc = Vf + (size_t)(y0 + dy) * WW + xt;
                #pragma unroll 1
                for (int u = tid; u < KK * 8; u += NTHREADS) {
                    int i = u >> 3, q = u & 7;
                    cp_async16(sV + i * 32 + q * 4, vsrc + (size_t)i * HWSZ + q * 4);
                }
                if (!(f == 1 && dy == TY - 1)) {
                    const float* hsrc = (dy < TY - 1)
                        ? Hf  + (size_t)(y0 + dy + 1) * WW + xt
                        : HfN + (size_t)y0 * WW + xt;
                    #pragma unroll 1
                    for (int u = tid; u < KK * 8; u += NTHREADS) {
                        int i = u >> 3, q = u & 7;
                        cp_async16(sH + i * 32 + q * 4, hsrc + (size_t)i * HWSZ + q * 4);
                    }
                }
                cp_commit();
            }

            // ---- MMA: warp w computes C rows [16w,16w+16), 32 cols.
            //      Band-aware split-K: nb 0,1 (n<16) live in ks 0..8;
            //      nb 2,3 (n>=16) live in ks 2..10. Skipped terms are exact 0.
            float d[4][4];
            #pragma unroll
            for (int nb = 0; nb < 4; nb++)
                #pragma unroll
                for (int e = 0; e < 4; e++) d[nb][e] = 0.0f;

            const unsigned* pa0 = sAu + (baseA + dy) * ASTR + t4;
            const unsigned* pa1 = sAu + (baseB + dy) * ASTR + t4;
            const unsigned* pb  = sB + t4 * BSTR + g;

            #pragma unroll
            for (int ks = 0; ks < 11; ks++) {
                const int c8 = ks * 8;
                unsigned a0 = pa0[c8];
                unsigned a1 = pa1[c8];
                unsigned a2 = pa0[c8 + 4];
                unsigned a3 = pa1[c8 + 4];
                if (ks <= 8) {
                    unsigned b00 = pb[(c8)     * BSTR];
                    unsigned b01 = pb[(c8 + 4) * BSTR];
                    unsigned b10 = pb[(c8)     * BSTR + 8];
                    unsigned b11 = pb[(c8 + 4) * BSTR + 8];
                    mma_m16n8k8(d[0], a0, a1, a2, a3, b00, b01);
                    mma_m16n8k8(d[1], a0, a1, a2, a3, b10, b11);
                }
                if (ks >= 2) {
                    unsigned b20 = pb[(c8)     * BSTR + 16];
                    unsigned b21 = pb[(c8 + 4) * BSTR + 16];
                    unsigned b30 = pb[(c8)     * BSTR + 24];
                    unsigned b31 = pb[(c8 + 4) * BSTR + 24];
                    mma_m16n8k8(d[2], a0, a1, a2, a3, b20, b21);
                    mma_m16n8k8(d[3], a0, a1, a2, a3, b30, b31);
                }
            }

            // ---- Store C ----
            #pragma unroll
            for (int nb = 0; nb < 4; nb++) {
                const int cc = 8 * nb + 2 * t4;
                *(float2*)&sC[r0 * CSTR + cc]       = make_float2(d[nb][0], d[nb][1]);
                *(float2*)&sC[(r0 + 8) * CSTR + cc] = make_float2(d[nb][2], d[nb][3]);
            }

            cp_wait0();              // V (+ next H) landed
            __syncthreads();         // barrier2: C + V + H visible

            // ---- Reduce: out(c,x) (+)= sum_i sV[i,x] * C[51c+i, x] ----
            if (tid < 96) {
                const float* cp_ = sC + (size_t)(51 * ec) * CSTR + xl;
                const float* vp  = sV + xl;
                float s0 = 0.0f, s1 = 0.0f;
                #pragma unroll
                for (int i = 0; i < 50; i += 2) {
                    s0 += vp[i * 32]       * cp_[i * CSTR];
                    s1 += vp[(i + 1) * 32] * cp_[(i + 1) * CSTR];
                }
                s0 += vp[50 * 32] * cp_[50 * CSTR];
                float s = s0 + s1;
                float* op = out + ((size_t)(b * 3 + ec) * HH + (y0 + dy)) * WW + xt + xl;
                if (f == 0) *op = s;
                else        *op = *op + s;      // same thread wrote it in f==0
            }
        }
    }
}

// ---------------------------------------------------------------------------
// kernel_launch: inputs are frame0, frame2, V1, H1, V2, H2 (metadata order).
// ---------------------------------------------------------------------------
extern "C" void kernel_launch(void* const* d_in, const int* in_sizes, int n_in,
                              void* d_out, int out_size) {
    const float* frame0 = (const float*)d_in[0];
    const float* frame2 = (const float*)d_in[1];
    const float* V1     = (const float*)d_in[2];
    const float* H1     = (const float*)d_in[3];
    const float* V2     = (const float*)d_in[4];
    const float* H2     = (const float*)d_in[5];
    float* out = (float*)d_out;

    cudaFuncSetAttribute(sepconv_mma,
                         cudaFuncAttributeMaxDynamicSharedMemorySize, SMEM_BYTES);

    const long total = 2L * 2 * 3 * PR * PSTR;
    pad_kernel<<<(int)((total + 255) / 256), 256>>>(frame0, frame2);

    dim3 grid(HH / TY, 16, 2);     // (y block, x-tile, batch)
    sepconv_mma<<<grid, NTHREADS, SMEM_BYTES>>>(V1, H1, V2, H2, out);
}

// round 14
// speedup vs baseline: 2.9723x; 1.0596x over previous
#include <cuda_runtime.h>

// Problem constants
#define HH   512
#define WW   512
#define KK   51
#define PADK 25
#define PR   562          // padded rows
#define PSTR 576          // padded row stride (floats, 16B-aligned)
#define HWSZ (512*512)

// Tiling: TY output rows per CTA share one A stage
#define TY    8
#define AROWS 174         // 3 ch x 58 padded rows staged
#define ASTR  92          // A smem row stride (conflict-free fragment loads)
#define BSTR  40          // B smem row stride (8 mod 32 -> conflict-free)
#define CSTR  34          // C smem row stride

// smem layout (float indices)
#define SA_F   0
#define SB_F   (AROWS*ASTR)              // 16008
#define SC_F   (SB_F + 88*BSTR)          // 19528
#define SV_F   (SC_F + 160*CSTR)         // 24968
#define SH_F   (SV_F + KK*32)            // 26600
#define SP_F   (SH_F + KK*32)            // 28232 (96-float reduce partials)
#define SMEM_FLOATS (SP_F + 96)          // 28328
#define SMEM_BYTES  (SMEM_FLOATS*4)      // 113312 -> 2 CTAs/SM

#define NTHREADS 320      // 10 warps; warps 0..4 do m32n32 MMA slabs

// Pre-padded frames: [frame][batch][channel][row][col]  (15.5 MB scratch)
__device__ __align__(16) float g_pad[2][2][3][PR][PSTR];

// ---------------------------------------------------------------------------
// Pad kernel: replication-pad both frames into g_pad.
// ---------------------------------------------------------------------------
__global__ void pad_kernel(const float* __restrict__ f0,
                           const float* __restrict__ f2) {
    long idx = (long)blockIdx.x * blockDim.x + threadIdx.x;
    const long total = 2L * 2 * 3 * PR * PSTR;
    if (idx >= total) return;
    int col = (int)(idx % PSTR);
    long r  = idx / PSTR;
    int row = (int)(r % PR); r /= PR;
    int c   = (int)(r % 3);  r /= 3;
    int b   = (int)(r % 2);  r /= 2;
    int f   = (int)r;
    int sy = row - PADK; sy = sy < 0 ? 0 : (sy > HH - 1 ? HH - 1 : sy);
    int sx = col - PADK; sx = sx < 0 ? 0 : (sx > WW - 1 ? WW - 1 : sx);
    const float* src = f ? f2 : f0;
    g_pad[f][b][c][row][col] = src[((size_t)(b * 3 + c) * HH + sy) * WW + sx];
}

// ---------------------------------------------------------------------------
// PTX helpers
// ---------------------------------------------------------------------------
__device__ __forceinline__ void cp_async16(void* smem_dst, const void* gmem_src) {
    unsigned saddr = (unsigned)__cvta_generic_to_shared(smem_dst);
    asm volatile("cp.async.cg.shared.global [%0], [%1], 16;\n"
                 :: "r"(saddr), "l"(gmem_src));
}
__device__ __forceinline__ void cp_commit() {
    asm volatile("cp.async.commit_group;\n" ::: "memory");
}
__device__ __forceinline__ void cp_wait0() {
    asm volatile("cp.async.wait_group 0;\n" ::: "memory");
}
__device__ __forceinline__ unsigned f2tf(float f) {        // fp32 -> tf32 (RN)
    unsigned r;
    asm("cvt.rna.tf32.f32 %0, %1;" : "=r"(r) : "f"(f));
    return r;
}
__device__ __forceinline__ void mma_m16n8k8(float d[4],
                                            unsigned a0, unsigned a1,
                                            unsigned a2, unsigned a3,
                                            unsigned b0, unsigned b1) {
    asm volatile(
        "mma.sync.aligned.m16n8k8.row.col.f32.tf32.tf32.f32 "
        "{%0,%1,%2,%3}, {%4,%5,%6,%7}, {%8,%9}, {%0,%1,%2,%3};"
        : "+f"(d[0]), "+f"(d[1]), "+f"(d[2]), "+f"(d[3])
        : "r"(a0), "r"(a1), "r"(a2), "r"(a3), "r"(b0), "r"(b1));
}

// ---------------------------------------------------------------------------
// Main kernel: one CTA per (8-row y block, x-tile of 32, batch).
// Banded tf32 GEMM per output row. GEMM by 5 warps x m32n32 (halves the
// duplicated B-fragment smem traffic); band-aware split-K skips exact zeros.
// V-reduce split across 192 threads.
// ---------------------------------------------------------------------------
__global__ void __launch_bounds__(NTHREADS, 2) sepconv_mma(
    const float* __restrict__ V1, const float* __restrict__ H1,
    const float* __restrict__ V2, const float* __restrict__ H2,
    float* __restrict__ out)
{
    extern __shared__ __align__(16) float smem[];
    float*    sA  = smem + SA_F;                // [174][92] fp32, then tf32 bits
    unsigned* sAu = (unsigned*)(smem + SA_F);
    unsigned* sB  = (unsigned*)(smem + SB_F);   // [88][40] tf32 bits
    float*    sC  = smem + SC_F;                // [160][34]
    float*    sV  = smem + SV_F;                // [51][32] V taps (this dy)
    float*    sH  = smem + SH_F;                // [51][32] H taps (next fillB)
    float*    spart = smem + SP_F;              // [96] reduce partials

    const int tid  = threadIdx.x;
    const int w    = tid >> 5;
    const int lane = tid & 31;
    const int g    = lane >> 2;      // groupID 0..7
    const int t4   = lane & 3;       // thread-in-group 0..3
    const int y0 = blockIdx.x * TY;
    const int xt = blockIdx.y * 32;
    const int b  = blockIdx.z;

    // m32 fragment row mapping: GEMM rows 32w + 8h + g (h=0..3), clamped
    int sabase[4];
    #pragma unroll
    for (int h = 0; h < 4; h++) {
        int r = 32 * (w < 5 ? w : 0) + 8 * h + g;
        if (r > 152) r = 152;
        int c = (r >= 102) ? 2 : (r >= 51 ? 1 : 0);
        sabase[h] = (c * 58 + (r - 51 * c)) * ASTR + t4;
    }

    // B-band j range per warp (all 10 warps fill)
    const int j0 = (w * KK) / 10;
    const int j1 = ((w + 1) * KK) / 10;

    // Zero B (band overwritten each dy; complement stays 0)
    #pragma unroll 1
    for (int u = tid; u < 88 * BSTR; u += NTHREADS) sB[u] = 0u;

    // Prologue: prefetch H(frame0, dy0) into sH
    {
        const float* h0 = H1 + (size_t)b * KK * HWSZ + (size_t)y0 * WW + xt;
        #pragma unroll 1
        for (int u = tid; u < KK * 8; u += NTHREADS) {
            int i = u >> 3, q = u & 7;
            cp_async16(sH + i * 32 + q * 4, h0 + (size_t)i * HWSZ + q * 4);
        }
        cp_commit();
    }

    #pragma unroll 1
    for (int f = 0; f < 2; f++) {
        const float* Vf   = (f ? V2 : V1) + (size_t)b * KK * HWSZ;
        const float* Hf   = (f ? H2 : H1) + (size_t)b * KK * HWSZ;
        const float* HfN  = H2 + (size_t)b * KK * HWSZ;   // next-frame H (f==0)
        const float* padB = &g_pad[f][b][0][0][0];

        // ---- Stage A once per frame: 174 rows x 22 float4 ----
        #pragma unroll 1
        for (int u = tid; u < AROWS * 22; u += NTHREADS) {
            int r = u / 22, q = u - r * 22;
            int c = r / 58, rr = r - c * 58;
            cp_async16(sA + r * ASTR + q * 4,
                       padB + ((size_t)c * PR + (y0 + rr)) * PSTR + xt + q * 4);
        }
        cp_commit();

        #pragma unroll 1
        for (int dy = 0; dy < TY; dy++) {
            if (dy == 0) {
                cp_wait0();
                __syncthreads();     // A (+H at f==0) visible to all threads
                // One-time in-place tf32 convert of sA
                #pragma unroll 1
                for (int u = tid; u < AROWS * 22; u += NTHREADS) {
                    int r = u / 22, q = u - r * 22;
                    float4* p = (float4*)(sA + r * ASTR + q * 4);
                    float4 v = *p;
                    uint4 t;
                    t.x = f2tf(v.x); t.y = f2tf(v.y);
                    t.z = f2tf(v.z); t.w = f2tf(v.w);
                    *(uint4*)p = t;
                }
            }

            // ---- Fill B band from smem H: B[n+j][n] = tf32(sH[j][n]) ----
            #pragma unroll 1
            for (int j = j0; j < j1; j++)
                sB[(lane + j) * BSTR + lane] = f2tf(sH[j * 32 + lane]);
            __syncthreads();         // barrier1: B + converted A ready

            // ---- Prefetch V(f,dy) and H(next) under the MMA shadow ----
            {
                const float* vsrc = Vf + (size_t)(y0 + dy) * WW + xt;
                #pragma unroll 1
                for (int u = tid; u < KK * 8; u += NTHREADS) {
                    int i = u >> 3, q = u & 7;
                    cp_async16(sV + i * 32 + q * 4, vsrc + (size_t)i * HWSZ + q * 4);
                }
                if (!(f == 1 && dy == TY - 1)) {
                    const float* hsrc = (dy < TY - 1)
                        ? Hf  + (size_t)(y0 + dy + 1) * WW + xt
                        : HfN + (size_t)y0 * WW + xt;
                    #pragma unroll 1
                    for (int u = tid; u < KK * 8; u += NTHREADS) {
                        int i = u >> 3, q = u & 7;
                        cp_async16(sH + i * 32 + q * 4, hsrc + (size_t)i * HWSZ + q * 4);
                    }
                }
                cp_commit();
            }

            // ---- MMA: warps 0..4, m32n32 each. Band-aware split-K:
            //      n<16 -> ks 0..8; n>=16 -> ks 2..10 (skipped terms exact 0).
            if (w < 5) {
                float d[4][2][4];
                #pragma unroll
                for (int nb = 0; nb < 4; nb++)
                    #pragma unroll
                    for (int h = 0; h < 2; h++)
                        #pragma unroll
                        for (int e = 0; e < 4; e++) d[nb][h][e] = 0.0f;

                const int dyo = dy * ASTR;
                const unsigned* pb = sB + t4 * BSTR + g;

                #pragma unroll
                for (int ks = 0; ks < 11; ks++) {
                    const int c8 = ks * 8;
                    unsigned a00 = sAu[sabase[0] + dyo + c8];
                    unsigned a01 = sAu[sabase[1] + dyo + c8];
                    unsigned a02 = sAu[sabase[0] + dyo + c8 + 4];
                    unsigned a03 = sAu[sabase[1] + dyo + c8 + 4];
                    unsigned a10 = sAu[sabase[2] + dyo + c8];
                    unsigned a11 = sAu[sabase[3] + dyo + c8];
                    unsigned a12 = sAu[sabase[2] + dyo + c8 + 4];
                    unsigned a13 = sAu[sabase[3] + dyo + c8 + 4];
                    if (ks <= 8) {
                        unsigned b00 = pb[(c8)     * BSTR];
                        unsigned b01 = pb[(c8 + 4) * BSTR];
                        unsigned b10 = pb[(c8)     * BSTR + 8];
                        unsigned b11 = pb[(c8 + 4) * BSTR + 8];
                        mma_m16n8k8(d[0][0], a00, a01, a02, a03, b00, b01);
                        mma_m16n8k8(d[0][1], a10, a11, a12, a13, b00, b01);
                        mma_m16n8k8(d[1][0], a00, a01, a02, a03, b10, b11);
                        mma_m16n8k8(d[1][1], a10, a11, a12, a13, b10, b11);
                    }
                    if (ks >= 2) {
                        unsigned b20 = pb[(c8)     * BSTR + 16];
                        unsigned b21 = pb[(c8 + 4) * BSTR + 16];
                        unsigned b30 = pb[(c8)     * BSTR + 24];
                        unsigned b31 = pb[(c8 + 4) * BSTR + 24];
                        mma_m16n8k8(d[2][0], a00, a01, a02, a03, b20, b21);
                        mma_m16n8k8(d[2][1], a10, a11, a12, a13, b20, b21);
                        mma_m16n8k8(d[3][0], a00, a01, a02, a03, b30, b31);
                        mma_m16n8k8(d[3][1], a10, a11, a12, a13, b30, b31);
                    }
                }

                // ---- Store C: frag h covers rows 32w+16h+g and +8 ----
                #pragma unroll
                for (int nb = 0; nb < 4; nb++)
                    #pragma unroll
                    for (int h = 0; h < 2; h++) {
                        const int r  = 32 * w + 16 * h + g;
                        const int cc = 8 * nb + 2 * t4;
                        *(float2*)&sC[r * CSTR + cc] =
                            make_float2(d[nb][h][0], d[nb][h][1]);
                        *(float2*)&sC[(r + 8) * CSTR + cc] =
                            make_float2(d[nb][h][2], d[nb][h][3]);
                    }
            }

            cp_wait0();              // V (+ next H) landed
            __syncthreads();         // barrier2: C + V + H visible

            // ---- Reduce (192 threads): out(c,x) (+)= sum_i sV[i,x]*C[51c+i,x]
            float s = 0.0f;
            if (tid < 96) {
                const float* cp_ = sC + (size_t)(51 * (tid >> 5)) * CSTR + (tid & 31);
                const float* vp  = sV + (tid & 31);
                #pragma unroll
                for (int i = 0; i < 26; i++)
                    s += vp[i * 32] * cp_[i * CSTR];
            } else if (tid < 192) {
                const int p = tid - 96;
                const float* cp_ = sC + (size_t)(51 * (p >> 5) + 26) * CSTR + (p & 31);
                const float* vp  = sV + 26 * 32 + (p & 31);
                #pragma unroll
                for (int i = 0; i < 25; i++)
                    s += vp[i * 32] * cp_[i * CSTR];
                spart[p] = s;
            }
            __syncthreads();         // barrier3: partials visible

            if (tid < 96) {
                float tot = s + spart[tid];
                float* op = out + ((size_t)(b * 3 + (tid >> 5)) * HH + (y0 + dy)) * WW
                                + xt + (tid & 31);
                if (f == 0) *op = tot;
                else        *op = *op + tot;    // same thread wrote it in f==0
            }
        }
    }
}

// ---------------------------------------------------------------------------
// kernel_launch: inputs are frame0, frame2, V1, H1, V2, H2 (metadata order).
// ---------------------------------------------------------------------------
extern "C" void kernel_launch(void* const* d_in, const int* in_sizes, int n_in,
                              void* d_out, int out_size) {
    const float* frame0 = (const float*)d_in[0];
    const float* frame2 = (const float*)d_in[1];
    const float* V1     = (const float*)d_in[2];
    const float* H1     = (const float*)d_in[3];
    const float* V2     = (const float*)d_in[4];
    const float* H2     = (const float*)d_in[5];
    float* out = (float*)d_out;

    cudaFuncSetAttribute(sepconv_mma,
                         cudaFuncAttributeMaxDynamicSharedMemorySize, SMEM_BYTES);

    const long total = 2L * 2 * 3 * PR * PSTR;
    pad_kernel<<<(int)((total + 255) / 256), 256>>>(frame0, frame2);

    dim3 grid(HH / TY, 16, 2);     // (y block, x-tile, batch)
    sepconv_mma<<<grid, NTHREADS, SMEM_BYTES>>>(V1, H1, V2, H2, out);
}